// round 15
// baseline (speedup 1.0000x reference)
#include <cuda_runtime.h>
#include <cuda_bf16.h>
#include <cstdint>

// Problem constants (dataset fixed: N=50000, E=800000, IN=128, H=64, C=16)
#define MAXN 50016
#define MAXE 800000
#define H 64
#define IN_F 128
#define C_OUT 16

// Scratch (device globals; 16B aligned)
__device__ __align__(16) int   g_degi[MAXN];
__device__ __align__(16) int   g_rowptr[MAXN];
__device__ __align__(16) int   g_cursor[4];
__device__ __align__(16) int   g_col[MAXE];
__device__ __align__(16) float g_dinv[MAXN];
__device__ __align__(16) float g_hs1[MAXN * H];
__device__ __align__(16) float g_hs2[MAXN * H];
__device__ __align__(16) float g_A[MAXN * H];
__device__ __align__(16) float g_B[MAXN * H];

typedef unsigned long long ull;

__device__ __forceinline__ void ffma2(ull& acc, ull a, ull b) {
    asm("fma.rn.f32x2 %0, %1, %2, %0;" : "+l"(acc) : "l"(a), "l"(b));
}
__device__ __forceinline__ ull pk2(float a, float b) {
    ull r;
    asm("mov.b64 %0, {%1, %2};" : "=l"(r) : "f"(a), "f"(b));
    return r;
}
__device__ __forceinline__ float2 unpk(ull v) {
    float2 r;
    asm("mov.b64 {%0, %1}, %2;" : "=f"(r.x), "=f"(r.y) : "l"(v));
    return r;
}

// ---------------- CSR build (side stream, overlapped with gemm1)
__global__ void count_kernel(const int* __restrict__ dst, int E) {
    int e = blockIdx.x * blockDim.x + threadIdx.x;
    if (e < E) atomicAdd(&g_degi[dst[e]], 1);
}

// Warp-aggregated cursor allocation (1 atomic/warp) + dinv computation.
__global__ void assign_kernel(int N) {
    int n = blockIdx.x * blockDim.x + threadIdx.x;
    int lane = threadIdx.x & 31;
    int deg = (n < N) ? g_degi[n] : 0;

    int x = deg;
#pragma unroll
    for (int o = 1; o < 32; o <<= 1) {
        int y = __shfl_up_sync(0xffffffffu, x, o);
        if (lane >= o) x += y;
    }
    int total = __shfl_sync(0xffffffffu, x, 31);
    int base = 0;
    if (lane == 31) base = atomicAdd(&g_cursor[0], total);
    base = __shfl_sync(0xffffffffu, base, 31);

    if (n < N) {
        g_rowptr[n] = base + (x - deg);
        g_dinv[n] = rsqrtf((float)(deg + 1));
    }
}

// rowptr doubles as the fill cursor; after this kernel rowptr[n] = segment END.
__global__ void fill_kernel(const int* __restrict__ src, const int* __restrict__ dst, int E) {
    int e = blockIdx.x * blockDim.x + threadIdx.x;
    if (e >= E) return;
    int d = dst[e];
    int pos = atomicAdd(&g_rowptr[d], 1);
    g_col[pos] = src[e];
}

// gather one (node, chunk) item: returns dinv-weighted aggregation for chunk c
__device__ __forceinline__ float4 gather_item(const float* __restrict__ hs, int n, int c) {
    const float* hp = hs + c;
    float dn = g_dinv[n];
    float4 sv = *reinterpret_cast<const float4*>(hp + (size_t)n * H);
    float4 acc = make_float4(sv.x * dn, sv.y * dn, sv.z * dn, sv.w * dn);
    int end = g_rowptr[n];
    int i = end - g_degi[n];
    for (; i + 4 <= end; i += 4) {
        int s0 = __ldg(&g_col[i + 0]);
        int s1 = __ldg(&g_col[i + 1]);
        int s2 = __ldg(&g_col[i + 2]);
        int s3 = __ldg(&g_col[i + 3]);
        float d0 = __ldg(&g_dinv[s0]);
        float d1 = __ldg(&g_dinv[s1]);
        float d2 = __ldg(&g_dinv[s2]);
        float d3 = __ldg(&g_dinv[s3]);
        float4 v0 = *reinterpret_cast<const float4*>(hp + (size_t)s0 * H);
        float4 v1 = *reinterpret_cast<const float4*>(hp + (size_t)s1 * H);
        float4 v2 = *reinterpret_cast<const float4*>(hp + (size_t)s2 * H);
        float4 v3 = *reinterpret_cast<const float4*>(hp + (size_t)s3 * H);
        acc.x += v0.x * d0 + v1.x * d1 + v2.x * d2 + v3.x * d3;
        acc.y += v0.y * d0 + v1.y * d1 + v2.y * d2 + v3.y * d3;
        acc.z += v0.z * d0 + v1.z * d1 + v2.z * d2 + v3.z * d3;
        acc.w += v0.w * d0 + v1.w * d1 + v2.w * d2 + v3.w * d3;
    }
    for (; i < end; i++) {
        int s = __ldg(&g_col[i]);
        float ds = __ldg(&g_dinv[s]);
        float4 v = *reinterpret_cast<const float4*>(hp + (size_t)s * H);
        acc.x += v.x * ds; acc.y += v.y * ds; acc.z += v.z * ds; acc.w += v.w * ds;
    }
    // outer dinv[n]
    acc.x *= dn; acc.y *= dn; acc.z *= dn; acc.w *= dn;
    return acc;
}

#define GEMM_MAIN()                                                             \
    _Pragma("unroll 8")                                                         \
    for (int kk = 0; kk < 64; kk++) {                                           \
        float4 b4 = *reinterpret_cast<const float4*>(&Ws[kk][tx * 4]);          \
        float a0 = As[ty * 4 + 0][kk];                                          \
        float a1 = As[ty * 4 + 1][kk];                                          \
        float a2 = As[ty * 4 + 2][kk];                                          \
        float a3 = As[ty * 4 + 3][kk];                                          \
        acc[0][0] += a0 * b4.x; acc[0][1] += a0 * b4.y; acc[0][2] += a0 * b4.z; acc[0][3] += a0 * b4.w; \
        acc[1][0] += a1 * b4.x; acc[1][1] += a1 * b4.y; acc[1][2] += a1 * b4.z; acc[1][3] += a1 * b4.w; \
        acc[2][0] += a2 * b4.x; acc[2][1] += a2 * b4.y; acc[2][2] += a2 * b4.z; acc[2][3] += a2 * b4.w; \
        acc[3][0] += a3 * b4.x; acc[3][1] += a3 * b4.y; acc[3][2] += a3 * b4.z; acc[3][3] += a3 * b4.w; \
    }

// conv1: hs1 = x @ W1 (RAW — fully independent of CSR chain)
__global__ __launch_bounds__(256) void gemm1_tiled(
    const float* __restrict__ x, const float* __restrict__ W1, int N) {
    __shared__ float As[64][68];
    __shared__ float Ws[64][68];
    const int tx = threadIdx.x, ty = threadIdx.y;
    const int t = ty * 16 + tx;
    const int lm = t >> 4;
    const int lk4 = (t & 15) * 4;
    const int m0 = blockIdx.x * 64;

    float acc[4][4];
#pragma unroll
    for (int i = 0; i < 4; i++)
#pragma unroll
        for (int j = 0; j < 4; j++) acc[i][j] = 0.f;

    for (int k0 = 0; k0 < IN_F; k0 += 64) {
        __syncthreads();
#pragma unroll
        for (int i = 0; i < 4; i++) {
            int m = lm + 16 * i;
            int gm = m0 + m;
            float4 v = make_float4(0.f, 0.f, 0.f, 0.f);
            if (gm < N) v = *reinterpret_cast<const float4*>(x + (size_t)gm * IN_F + k0 + lk4);
            *reinterpret_cast<float4*>(&As[m][lk4]) = v;
            int k = lm + 16 * i;
            float4 w = *reinterpret_cast<const float4*>(W1 + (size_t)(k0 + k) * H + lk4);
            *reinterpret_cast<float4*>(&Ws[k][lk4]) = w;
        }
        __syncthreads();
        GEMM_MAIN()
    }

#pragma unroll
    for (int i = 0; i < 4; i++) {
        int gm = m0 + ty * 4 + i;
        if (gm < N) {
            float4 r = make_float4(acc[i][0], acc[i][1], acc[i][2], acc[i][3]);
            *reinterpret_cast<float4*>(&g_hs1[(size_t)gm * H + tx * 4]) = r;
        }
    }
}

// fused conv2: gather(hs1) -> relu(.+b1) -> smem -> GEMM W2 -> hs2 (raw)
__global__ __launch_bounds__(256) void fused_gg2(
    const float* __restrict__ hs_in, const float* __restrict__ b1,
    const float* __restrict__ W2, float* __restrict__ hs_out, int N) {
    __shared__ float As[64][68];
    __shared__ float Ws[64][68];
    const int t = threadIdx.x;
    const int tx = t & 15, ty = t >> 4;
    const int m0 = blockIdx.x * 64;

    // load weights (each thread 16 floats, same mapping as before)
    {
        const int lm = t >> 4;
        const int lk4 = (t & 15) * 4;
#pragma unroll
        for (int i = 0; i < 4; i++) {
            int k = lm + 16 * i;
            float4 w = *reinterpret_cast<const float4*>(W2 + (size_t)k * H + lk4);
            *reinterpret_cast<float4*>(&Ws[k][lk4]) = w;
        }
    }

    // gather phase: 1024 items (64 nodes x 16 chunks), 4 per thread
#pragma unroll
    for (int it = 0; it < 4; it++) {
        int item = t + 256 * it;
        int m = item >> 4;
        int c = (item & 15) << 2;
        int gm = m0 + m;
        float4 v = make_float4(0.f, 0.f, 0.f, 0.f);
        if (gm < N) {
            float4 agg = gather_item(hs_in, gm, c);
            float4 bb = *reinterpret_cast<const float4*>(b1 + c);
            v.x = fmaxf(agg.x + bb.x, 0.f);
            v.y = fmaxf(agg.y + bb.y, 0.f);
            v.z = fmaxf(agg.z + bb.z, 0.f);
            v.w = fmaxf(agg.w + bb.w, 0.f);
        }
        *reinterpret_cast<float4*>(&As[m][c]) = v;
    }
    __syncthreads();

    float acc[4][4];
#pragma unroll
    for (int i = 0; i < 4; i++)
#pragma unroll
        for (int j = 0; j < 4; j++) acc[i][j] = 0.f;

    GEMM_MAIN()

#pragma unroll
    for (int i = 0; i < 4; i++) {
        int gm = m0 + ty * 4 + i;
        if (gm < N) {
            float4 r = make_float4(acc[i][0], acc[i][1], acc[i][2], acc[i][3]);
            *reinterpret_cast<float4*>(&hs_out[(size_t)gm * H + tx * 4]) = r;
        }
    }
}

// fused conv3: gather(hs2) -> relu(.+b2) -> smem -> GEMM both Wm1 halves
// g_A = h2 @ Wm1[0:64] + bm1 ; g_B = h2 @ Wm1[64:128]
__global__ __launch_bounds__(256) void fused_gg3(
    const float* __restrict__ hs_in, const float* __restrict__ b2,
    const float* __restrict__ Wm1, const float* __restrict__ bm1, int N) {
    __shared__ float As[64][68];
    __shared__ float Ws[64][68];
    const int t = threadIdx.x;
    const int tx = t & 15, ty = t >> 4;
    const int lm = t >> 4;
    const int lk4 = (t & 15) * 4;
    const int m0 = blockIdx.x * 64;

    // load half-0 weights
#pragma unroll
    for (int i = 0; i < 4; i++) {
        int k = lm + 16 * i;
        float4 w = *reinterpret_cast<const float4*>(Wm1 + (size_t)k * H + lk4);
        *reinterpret_cast<float4*>(&Ws[k][lk4]) = w;
    }

    // gather phase
#pragma unroll
    for (int it = 0; it < 4; it++) {
        int item = t + 256 * it;
        int m = item >> 4;
        int c = (item & 15) << 2;
        int gm = m0 + m;
        float4 v = make_float4(0.f, 0.f, 0.f, 0.f);
        if (gm < N) {
            float4 agg = gather_item(hs_in, gm, c);
            float4 bb = *reinterpret_cast<const float4*>(b2 + c);
            v.x = fmaxf(agg.x + bb.x, 0.f);
            v.y = fmaxf(agg.y + bb.y, 0.f);
            v.z = fmaxf(agg.z + bb.z, 0.f);
            v.w = fmaxf(agg.w + bb.w, 0.f);
        }
        *reinterpret_cast<float4*>(&As[m][c]) = v;
    }
    __syncthreads();

    // half 0 -> g_A (+bm1)
    {
        float acc[4][4];
#pragma unroll
        for (int i = 0; i < 4; i++)
#pragma unroll
            for (int j = 0; j < 4; j++) acc[i][j] = 0.f;
        GEMM_MAIN()
        float4 badd = *reinterpret_cast<const float4*>(bm1 + tx * 4);
#pragma unroll
        for (int i = 0; i < 4; i++) {
            int gm = m0 + ty * 4 + i;
            if (gm < N) {
                float4 r = make_float4(acc[i][0] + badd.x, acc[i][1] + badd.y,
                                       acc[i][2] + badd.z, acc[i][3] + badd.w);
                *reinterpret_cast<float4*>(&g_A[(size_t)gm * H + tx * 4]) = r;
            }
        }
    }

    __syncthreads();
#pragma unroll
    for (int i = 0; i < 4; i++) {
        int k = lm + 16 * i;
        float4 w = *reinterpret_cast<const float4*>(Wm1 + (size_t)(H + k) * H + lk4);
        *reinterpret_cast<float4*>(&Ws[k][lk4]) = w;
    }
    __syncthreads();

    // half 1 -> g_B
    {
        float acc[4][4];
#pragma unroll
        for (int i = 0; i < 4; i++)
#pragma unroll
            for (int j = 0; j < 4; j++) acc[i][j] = 0.f;
        GEMM_MAIN()
#pragma unroll
        for (int i = 0; i < 4; i++) {
            int gm = m0 + ty * 4 + i;
            if (gm < N) {
                float4 r = make_float4(acc[i][0], acc[i][1], acc[i][2], acc[i][3]);
                *reinterpret_cast<float4*>(&g_B[(size_t)gm * H + tx * 4]) = r;
            }
        }
    }
}

// ---------------- edge MLP: out[e] = relu(A[src]+B[dst]) @ Wm2 + bm2 (f32x2)
__global__ void edge_kernel(const int* __restrict__ src, const int* __restrict__ dst,
                            const float* __restrict__ Wm2, const float* __restrict__ bm2,
                            float* __restrict__ out, int E) {
    __shared__ float Ws[H * C_OUT];
    __shared__ float bs[C_OUT];
    int tid = threadIdx.x;
    for (int i = tid; i < H * C_OUT; i += blockDim.x) Ws[i] = Wm2[i];
    if (tid < C_OUT) bs[tid] = bm2[tid];
    __syncthreads();

    int e = blockIdx.x * blockDim.x + tid;
    if (e >= E) return;
    int s = src[e], d = dst[e];
    const float4* Ap = reinterpret_cast<const float4*>(g_A + (size_t)s * H);
    const float4* Bp = reinterpret_cast<const float4*>(g_B + (size_t)d * H);

    ull acc2[8];
#pragma unroll
    for (int j = 0; j < 8; j++) acc2[j] = pk2(bs[2 * j], bs[2 * j + 1]);

#pragma unroll
    for (int q = 0; q < H / 4; q++) {
        float4 a4 = Ap[q];
        float4 b4 = Bp[q];
        ull zp[4];
        zp[0] = pk2(fmaxf(a4.x + b4.x, 0.f), fmaxf(a4.x + b4.x, 0.f));
        zp[1] = pk2(fmaxf(a4.y + b4.y, 0.f), fmaxf(a4.y + b4.y, 0.f));
        zp[2] = pk2(fmaxf(a4.z + b4.z, 0.f), fmaxf(a4.z + b4.z, 0.f));
        zp[3] = pk2(fmaxf(a4.w + b4.w, 0.f), fmaxf(a4.w + b4.w, 0.f));
#pragma unroll
        for (int kk = 0; kk < 4; kk++) {
            const ulonglong2* wrow = reinterpret_cast<const ulonglong2*>(Ws + (q * 4 + kk) * C_OUT);
#pragma unroll
            for (int j = 0; j < 4; j++) {
                ulonglong2 w2 = wrow[j];
                ffma2(acc2[2 * j + 0], zp[kk], w2.x);
                ffma2(acc2[2 * j + 1], zp[kk], w2.y);
            }
        }
    }

    float4* op = reinterpret_cast<float4*>(out + (size_t)e * C_OUT);
#pragma unroll
    for (int c = 0; c < 4; c++) {
        float2 p0 = unpk(acc2[2 * c + 0]);
        float2 p1 = unpk(acc2[2 * c + 1]);
        op[c] = make_float4(p0.x, p0.y, p1.x, p1.y);
    }
}

extern "C" void kernel_launch(void* const* d_in, const int* in_sizes, int n_in,
                              void* d_out, int out_size) {
    const float* x    = (const float*)d_in[0];
    const int*   ei   = (const int*)d_in[1];
    const float* W1   = (const float*)d_in[2];
    const float* b1   = (const float*)d_in[3];
    const float* W2   = (const float*)d_in[4];
    const float* b2   = (const float*)d_in[5];
    const float* Wm1  = (const float*)d_in[6];
    const float* bm1  = (const float*)d_in[7];
    const float* Wm2  = (const float*)d_in[8];
    const float* bm2  = (const float*)d_in[9];
    float* out = (float*)d_out;

    int N = in_sizes[0] / IN_F;
    int E = in_sizes[1] / 2;
    const int* src = ei;
    const int* dst = ei + E;

    int*   degi;   cudaGetSymbolAddress((void**)&degi,   g_degi);
    int*   cursor; cudaGetSymbolAddress((void**)&cursor, g_cursor);
    float* hs1;  cudaGetSymbolAddress((void**)&hs1,  g_hs1);
    float* hs2;  cudaGetSymbolAddress((void**)&hs2,  g_hs2);

    int blocks_m = (N + 63) / 64;

    // Side stream + fork/join events (capture-time only)
    cudaStream_t s2;
    cudaEvent_t evFork, evCsr;
    cudaStreamCreateWithFlags(&s2, cudaStreamNonBlocking);
    cudaEventCreateWithFlags(&evFork, cudaEventDisableTiming);
    cudaEventCreateWithFlags(&evCsr,  cudaEventDisableTiming);

    // fork: CSR build on s2 || gemm1 on main
    cudaEventRecord(evFork, 0);
    cudaStreamWaitEvent(s2, evFork, 0);
    cudaMemsetAsync(degi, 0, (size_t)N * sizeof(int), s2);
    cudaMemsetAsync(cursor, 0, 4 * sizeof(int), s2);
    count_kernel<<<(E + 255) / 256, 256, 0, s2>>>(dst, E);
    assign_kernel<<<(N + 255) / 256, 256, 0, s2>>>(N);
    fill_kernel<<<(E + 255) / 256, 256, 0, s2>>>(src, dst, E);
    cudaEventRecord(evCsr, s2);

    gemm1_tiled<<<blocks_m, dim3(16, 16)>>>(x, W1, N);
    cudaStreamWaitEvent(0, evCsr, 0);

    // fused conv2: gather + GEMM
    fused_gg2<<<blocks_m, 256>>>(hs1, b1, W2, hs2, N);

    // fused conv3: gather + GEMM (both halves)
    fused_gg3<<<blocks_m, 256>>>(hs2, b2, Wm1, bm1, N);

    // edge MLP
    edge_kernel<<<(E + 255) / 256, 256>>>(src, dst, Wm2, bm2, out, E);
}

// round 16
// speedup vs baseline: 1.0107x; 1.0107x over previous
#include <cuda_runtime.h>
#include <cuda_bf16.h>
#include <cstdint>

// Problem constants (dataset fixed: N=50000, E=800000, IN=128, H=64, C=16)
#define MAXN 50016
#define MAXE 800000
#define H 64
#define IN_F 128
#define C_OUT 16

// Scratch (device globals; 16B aligned)
__device__ __align__(16) int   g_degi[MAXN];
__device__ __align__(16) int   g_rowptr[MAXN];
__device__ __align__(16) int   g_cursor[4];
__device__ __align__(16) int   g_col[MAXE];
__device__ __align__(16) float g_dinv[MAXN];
__device__ __align__(16) float g_hs1[MAXN * H];
__device__ __align__(16) float g_acc1[MAXN * H];
__device__ __align__(16) float g_hs2[MAXN * H];
__device__ __align__(16) float g_acc2[MAXN * H];
__device__ __align__(16) float g_A[MAXN * H];
__device__ __align__(16) float g_B[MAXN * H];

typedef unsigned long long ull;

__device__ __forceinline__ void ffma2(ull& acc, ull a, ull b) {
    asm("fma.rn.f32x2 %0, %1, %2, %0;" : "+l"(acc) : "l"(a), "l"(b));
}
__device__ __forceinline__ ull pk2(float a, float b) {
    ull r;
    asm("mov.b64 %0, {%1, %2};" : "=l"(r) : "f"(a), "f"(b));
    return r;
}
__device__ __forceinline__ float2 unpk(ull v) {
    float2 r;
    asm("mov.b64 {%0, %1}, %2;" : "=f"(r.x), "=f"(r.y) : "l"(v));
    return r;
}

// ---------------- CSR build (side stream, overlapped with gemm1)
__global__ void count_kernel(const int* __restrict__ dst, int E) {
    int e = blockIdx.x * blockDim.x + threadIdx.x;
    if (e < E) atomicAdd(&g_degi[dst[e]], 1);
}

// Warp-aggregated cursor allocation (1 atomic/warp) + dinv computation.
__global__ void assign_kernel(int N) {
    int n = blockIdx.x * blockDim.x + threadIdx.x;
    int lane = threadIdx.x & 31;
    int deg = (n < N) ? g_degi[n] : 0;

    int x = deg;
#pragma unroll
    for (int o = 1; o < 32; o <<= 1) {
        int y = __shfl_up_sync(0xffffffffu, x, o);
        if (lane >= o) x += y;
    }
    int total = __shfl_sync(0xffffffffu, x, 31);
    int base = 0;
    if (lane == 31) base = atomicAdd(&g_cursor[0], total);
    base = __shfl_sync(0xffffffffu, base, 31);

    if (n < N) {
        g_rowptr[n] = base + (x - deg);
        g_dinv[n] = rsqrtf((float)(deg + 1));
    }
}

// rowptr doubles as the fill cursor; after this kernel rowptr[n] = segment END.
__global__ void fill_kernel(const int* __restrict__ src, const int* __restrict__ dst, int E) {
    int e = blockIdx.x * blockDim.x + threadIdx.x;
    if (e >= E) return;
    int d = dst[e];
    int pos = atomicAdd(&g_rowptr[d], 1);
    g_col[pos] = src[e];
}

// ---------------- weighted gather (conv1): out[n] = raw[n]*dinv[n] + sum raw[s]*dinv[s]
__global__ void gather_w_kernel(const float* __restrict__ hs, float* __restrict__ out, int N) {
    int t = blockIdx.x * blockDim.x + threadIdx.x;
    int n = t >> 4;
    if (n >= N) return;
    int c = (t & 15) << 2;
    const float* hp = hs + c;

    float dn = g_dinv[n];
    float4 sv = *reinterpret_cast<const float4*>(hp + (size_t)n * H);
    float4 acc = make_float4(sv.x * dn, sv.y * dn, sv.z * dn, sv.w * dn);

    int end = g_rowptr[n];
    int i = end - g_degi[n];
    for (; i + 8 <= end; i += 8) {
        int s0 = __ldg(&g_col[i + 0]);
        int s1 = __ldg(&g_col[i + 1]);
        int s2 = __ldg(&g_col[i + 2]);
        int s3 = __ldg(&g_col[i + 3]);
        int s4 = __ldg(&g_col[i + 4]);
        int s5 = __ldg(&g_col[i + 5]);
        int s6 = __ldg(&g_col[i + 6]);
        int s7 = __ldg(&g_col[i + 7]);
        float d0 = __ldg(&g_dinv[s0]);
        float d1 = __ldg(&g_dinv[s1]);
        float d2 = __ldg(&g_dinv[s2]);
        float d3 = __ldg(&g_dinv[s3]);
        float d4 = __ldg(&g_dinv[s4]);
        float d5 = __ldg(&g_dinv[s5]);
        float d6 = __ldg(&g_dinv[s6]);
        float d7 = __ldg(&g_dinv[s7]);
        float4 v0 = *reinterpret_cast<const float4*>(hp + (size_t)s0 * H);
        float4 v1 = *reinterpret_cast<const float4*>(hp + (size_t)s1 * H);
        float4 v2 = *reinterpret_cast<const float4*>(hp + (size_t)s2 * H);
        float4 v3 = *reinterpret_cast<const float4*>(hp + (size_t)s3 * H);
        float4 v4 = *reinterpret_cast<const float4*>(hp + (size_t)s4 * H);
        float4 v5 = *reinterpret_cast<const float4*>(hp + (size_t)s5 * H);
        float4 v6 = *reinterpret_cast<const float4*>(hp + (size_t)s6 * H);
        float4 v7 = *reinterpret_cast<const float4*>(hp + (size_t)s7 * H);
        acc.x += v0.x * d0 + v1.x * d1 + v2.x * d2 + v3.x * d3
               + v4.x * d4 + v5.x * d5 + v6.x * d6 + v7.x * d7;
        acc.y += v0.y * d0 + v1.y * d1 + v2.y * d2 + v3.y * d3
               + v4.y * d4 + v5.y * d5 + v6.y * d6 + v7.y * d7;
        acc.z += v0.z * d0 + v1.z * d1 + v2.z * d2 + v3.z * d3
               + v4.z * d4 + v5.z * d5 + v6.z * d6 + v7.z * d7;
        acc.w += v0.w * d0 + v1.w * d1 + v2.w * d2 + v3.w * d3
               + v4.w * d4 + v5.w * d5 + v6.w * d6 + v7.w * d7;
    }
    for (; i < end; i++) {
        int s = __ldg(&g_col[i]);
        float ds = __ldg(&g_dinv[s]);
        float4 v = *reinterpret_cast<const float4*>(hp + (size_t)s * H);
        acc.x += v.x * ds; acc.y += v.y * ds; acc.z += v.z * ds; acc.w += v.w * ds;
    }
    *reinterpret_cast<float4*>(out + (size_t)n * H + c) = acc;
}

// ---------------- plain gather (conv2; hs already pre-scaled by dinv)
__global__ void gather_p_kernel(const float* __restrict__ hs, float* __restrict__ out, int N) {
    int t = blockIdx.x * blockDim.x + threadIdx.x;
    int n = t >> 4;
    if (n >= N) return;
    int c = (t & 15) << 2;
    const float* hp = hs + c;
    float4 acc = *reinterpret_cast<const float4*>(hp + (size_t)n * H);  // self
    int end = g_rowptr[n];
    int i = end - g_degi[n];
    for (; i + 8 <= end; i += 8) {
        int s0 = __ldg(&g_col[i + 0]);
        int s1 = __ldg(&g_col[i + 1]);
        int s2 = __ldg(&g_col[i + 2]);
        int s3 = __ldg(&g_col[i + 3]);
        int s4 = __ldg(&g_col[i + 4]);
        int s5 = __ldg(&g_col[i + 5]);
        int s6 = __ldg(&g_col[i + 6]);
        int s7 = __ldg(&g_col[i + 7]);
        float4 v0 = *reinterpret_cast<const float4*>(hp + (size_t)s0 * H);
        float4 v1 = *reinterpret_cast<const float4*>(hp + (size_t)s1 * H);
        float4 v2 = *reinterpret_cast<const float4*>(hp + (size_t)s2 * H);
        float4 v3 = *reinterpret_cast<const float4*>(hp + (size_t)s3 * H);
        float4 v4 = *reinterpret_cast<const float4*>(hp + (size_t)s4 * H);
        float4 v5 = *reinterpret_cast<const float4*>(hp + (size_t)s5 * H);
        float4 v6 = *reinterpret_cast<const float4*>(hp + (size_t)s6 * H);
        float4 v7 = *reinterpret_cast<const float4*>(hp + (size_t)s7 * H);
        acc.x += ((v0.x + v1.x) + (v2.x + v3.x)) + ((v4.x + v5.x) + (v6.x + v7.x));
        acc.y += ((v0.y + v1.y) + (v2.y + v3.y)) + ((v4.y + v5.y) + (v6.y + v7.y));
        acc.z += ((v0.z + v1.z) + (v2.z + v3.z)) + ((v4.z + v5.z) + (v6.z + v7.z));
        acc.w += ((v0.w + v1.w) + (v2.w + v3.w)) + ((v4.w + v5.w) + (v6.w + v7.w));
    }
    for (; i < end; i++) {
        int s = __ldg(&g_col[i]);
        float4 v = *reinterpret_cast<const float4*>(hp + (size_t)s * H);
        acc.x += v.x; acc.y += v.y; acc.z += v.z; acc.w += v.w;
    }
    *reinterpret_cast<float4*>(out + (size_t)n * H + c) = acc;
}

// =====================================================================
// Tiled GEMMs (R2 proven form): M=64, N=64, 256 thr, 4x4 microtile
// =====================================================================

#define GEMM_MAIN()                                                             \
    _Pragma("unroll 8")                                                         \
    for (int kk = 0; kk < 64; kk++) {                                           \
        float4 b4 = *reinterpret_cast<const float4*>(&Ws[kk][tx * 4]);          \
        float a0 = As[ty * 4 + 0][kk];                                          \
        float a1 = As[ty * 4 + 1][kk];                                          \
        float a2 = As[ty * 4 + 2][kk];                                          \
        float a3 = As[ty * 4 + 3][kk];                                          \
        acc[0][0] += a0 * b4.x; acc[0][1] += a0 * b4.y; acc[0][2] += a0 * b4.z; acc[0][3] += a0 * b4.w; \
        acc[1][0] += a1 * b4.x; acc[1][1] += a1 * b4.y; acc[1][2] += a1 * b4.z; acc[1][3] += a1 * b4.w; \
        acc[2][0] += a2 * b4.x; acc[2][1] += a2 * b4.y; acc[2][2] += a2 * b4.z; acc[2][3] += a2 * b4.w; \
        acc[3][0] += a3 * b4.x; acc[3][1] += a3 * b4.y; acc[3][2] += a3 * b4.z; acc[3][3] += a3 * b4.w; \
    }

// conv1: hs1 = x @ W1 (RAW — fully independent of CSR chain)
__global__ __launch_bounds__(256) void gemm1_tiled(
    const float* __restrict__ x, const float* __restrict__ W1, int N) {
    __shared__ float As[64][68];
    __shared__ float Ws[64][68];
    const int tx = threadIdx.x, ty = threadIdx.y;
    const int t = ty * 16 + tx;
    const int lm = t >> 4;
    const int lk4 = (t & 15) * 4;
    const int m0 = blockIdx.x * 64;

    float acc[4][4];
#pragma unroll
    for (int i = 0; i < 4; i++)
#pragma unroll
        for (int j = 0; j < 4; j++) acc[i][j] = 0.f;

    for (int k0 = 0; k0 < IN_F; k0 += 64) {
        __syncthreads();
#pragma unroll
        for (int i = 0; i < 4; i++) {
            int m = lm + 16 * i;
            int gm = m0 + m;
            float4 v = make_float4(0.f, 0.f, 0.f, 0.f);
            if (gm < N) v = *reinterpret_cast<const float4*>(x + (size_t)gm * IN_F + k0 + lk4);
            *reinterpret_cast<float4*>(&As[m][lk4]) = v;
            int k = lm + 16 * i;
            float4 w = *reinterpret_cast<const float4*>(W1 + (size_t)(k0 + k) * H + lk4);
            *reinterpret_cast<float4*>(&Ws[k][lk4]) = w;
        }
        __syncthreads();
        GEMM_MAIN()
    }

#pragma unroll
    for (int i = 0; i < 4; i++) {
        int gm = m0 + ty * 4 + i;
        if (gm < N) {
            float4 r = make_float4(acc[i][0], acc[i][1], acc[i][2], acc[i][3]);
            *reinterpret_cast<float4*>(&g_hs1[(size_t)gm * H + tx * 4]) = r;
        }
    }
}

// conv2: h1 = relu(acc1*dinv + b1); hs2 = (h1 @ W2) * dinv  (pre-scaled epilogue)
__global__ __launch_bounds__(256) void gemm2_tiled(
    const float* __restrict__ W2, const float* __restrict__ b1, int N) {
    __shared__ float As[64][68];
    __shared__ float Ws[64][68];
    const int tx = threadIdx.x, ty = threadIdx.y;
    const int t = ty * 16 + tx;
    const int lm = t >> 4;
    const int lk4 = (t & 15) * 4;
    const int m0 = blockIdx.x * 64;

    float4 bb = *reinterpret_cast<const float4*>(b1 + lk4);
#pragma unroll
    for (int i = 0; i < 4; i++) {
        int m = lm + 16 * i;
        int gm = m0 + m;
        float4 v = make_float4(0.f, 0.f, 0.f, 0.f);
        if (gm < N) {
            float di = g_dinv[gm];
            float4 a = *reinterpret_cast<const float4*>(&g_acc1[(size_t)gm * H + lk4]);
            v.x = fmaxf(a.x * di + bb.x, 0.f);
            v.y = fmaxf(a.y * di + bb.y, 0.f);
            v.z = fmaxf(a.z * di + bb.z, 0.f);
            v.w = fmaxf(a.w * di + bb.w, 0.f);
        }
        *reinterpret_cast<float4*>(&As[m][lk4]) = v;
        int k = lm + 16 * i;
        float4 w = *reinterpret_cast<const float4*>(W2 + (size_t)k * H + lk4);
        *reinterpret_cast<float4*>(&Ws[k][lk4]) = w;
    }
    __syncthreads();

    float acc[4][4];
#pragma unroll
    for (int i = 0; i < 4; i++)
#pragma unroll
        for (int j = 0; j < 4; j++) acc[i][j] = 0.f;

    GEMM_MAIN()

#pragma unroll
    for (int i = 0; i < 4; i++) {
        int gm = m0 + ty * 4 + i;
        if (gm < N) {
            float di = g_dinv[gm];
            float4 r = make_float4(acc[i][0] * di, acc[i][1] * di, acc[i][2] * di, acc[i][3] * di);
            *reinterpret_cast<float4*>(&g_hs2[(size_t)gm * H + tx * 4]) = r;
        }
    }
}

// node MLP precompute: h2 = relu(acc2*dinv + b2)
// half=0: g_A = h2 @ Wm1[0:64] + bm1 ; half=1: g_B = h2 @ Wm1[64:128]
__global__ __launch_bounds__(256) void gemm3_tiled(
    const float* __restrict__ Wm1, const float* __restrict__ b2,
    const float* __restrict__ bm1, int N) {
    __shared__ float As[64][68];
    __shared__ float Ws[64][68];
    const int tx = threadIdx.x, ty = threadIdx.y;
    const int t = ty * 16 + tx;
    const int lm = t >> 4;
    const int lk4 = (t & 15) * 4;
    const int m0 = blockIdx.x * 64;
    const int half = blockIdx.y;

    float4 bb = *reinterpret_cast<const float4*>(b2 + lk4);
#pragma unroll
    for (int i = 0; i < 4; i++) {
        int m = lm + 16 * i;
        int gm = m0 + m;
        float4 v = make_float4(0.f, 0.f, 0.f, 0.f);
        if (gm < N) {
            float di = g_dinv[gm];
            float4 a = *reinterpret_cast<const float4*>(&g_acc2[(size_t)gm * H + lk4]);
            v.x = fmaxf(a.x * di + bb.x, 0.f);
            v.y = fmaxf(a.y * di + bb.y, 0.f);
            v.z = fmaxf(a.z * di + bb.z, 0.f);
            v.w = fmaxf(a.w * di + bb.w, 0.f);
        }
        *reinterpret_cast<float4*>(&As[m][lk4]) = v;
        int k = lm + 16 * i;
        float4 w = *reinterpret_cast<const float4*>(Wm1 + (size_t)(half * H + k) * H + lk4);
        *reinterpret_cast<float4*>(&Ws[k][lk4]) = w;
    }
    __syncthreads();

    float acc[4][4];
#pragma unroll
    for (int i = 0; i < 4; i++)
#pragma unroll
        for (int j = 0; j < 4; j++) acc[i][j] = 0.f;

    GEMM_MAIN()

    float4 badd = make_float4(0.f, 0.f, 0.f, 0.f);
    if (half == 0) badd = *reinterpret_cast<const float4*>(bm1 + tx * 4);
    float* outbuf = (half == 0) ? g_A : g_B;
#pragma unroll
    for (int i = 0; i < 4; i++) {
        int gm = m0 + ty * 4 + i;
        if (gm < N) {
            float4 r = make_float4(acc[i][0] + badd.x, acc[i][1] + badd.y,
                                   acc[i][2] + badd.z, acc[i][3] + badd.w);
            *reinterpret_cast<float4*>(&outbuf[(size_t)gm * H + tx * 4]) = r;
        }
    }
}

// ---------------- edge MLP: out[e] = relu(A[src]+B[dst]) @ Wm2 + bm2 (f32x2)
__global__ void edge_kernel(const int* __restrict__ src, const int* __restrict__ dst,
                            const float* __restrict__ Wm2, const float* __restrict__ bm2,
                            float* __restrict__ out, int E) {
    __shared__ float Ws[H * C_OUT];
    __shared__ float bs[C_OUT];
    int tid = threadIdx.x;
    for (int i = tid; i < H * C_OUT; i += blockDim.x) Ws[i] = Wm2[i];
    if (tid < C_OUT) bs[tid] = bm2[tid];
    __syncthreads();

    int e = blockIdx.x * blockDim.x + tid;
    if (e >= E) return;
    int s = src[e], d = dst[e];
    const float4* Ap = reinterpret_cast<const float4*>(g_A + (size_t)s * H);
    const float4* Bp = reinterpret_cast<const float4*>(g_B + (size_t)d * H);

    ull acc2[8];
#pragma unroll
    for (int j = 0; j < 8; j++) acc2[j] = pk2(bs[2 * j], bs[2 * j + 1]);

#pragma unroll
    for (int q = 0; q < H / 4; q++) {
        float4 a4 = Ap[q];
        float4 b4 = Bp[q];
        ull zp[4];
        zp[0] = pk2(fmaxf(a4.x + b4.x, 0.f), fmaxf(a4.x + b4.x, 0.f));
        zp[1] = pk2(fmaxf(a4.y + b4.y, 0.f), fmaxf(a4.y + b4.y, 0.f));
        zp[2] = pk2(fmaxf(a4.z + b4.z, 0.f), fmaxf(a4.z + b4.z, 0.f));
        zp[3] = pk2(fmaxf(a4.w + b4.w, 0.f), fmaxf(a4.w + b4.w, 0.f));
#pragma unroll
        for (int kk = 0; kk < 4; kk++) {
            const ulonglong2* wrow = reinterpret_cast<const ulonglong2*>(Ws + (q * 4 + kk) * C_OUT);
#pragma unroll
            for (int j = 0; j < 4; j++) {
                ulonglong2 w2 = wrow[j];
                ffma2(acc2[2 * j + 0], zp[kk], w2.x);
                ffma2(acc2[2 * j + 1], zp[kk], w2.y);
            }
        }
    }

    float4* op = reinterpret_cast<float4*>(out + (size_t)e * C_OUT);
#pragma unroll
    for (int c = 0; c < 4; c++) {
        float2 p0 = unpk(acc2[2 * c + 0]);
        float2 p1 = unpk(acc2[2 * c + 1]);
        op[c] = make_float4(p0.x, p0.y, p1.x, p1.y);
    }
}

extern "C" void kernel_launch(void* const* d_in, const int* in_sizes, int n_in,
                              void* d_out, int out_size) {
    const float* x    = (const float*)d_in[0];
    const int*   ei   = (const int*)d_in[1];
    const float* W1   = (const float*)d_in[2];
    const float* b1   = (const float*)d_in[3];
    const float* W2   = (const float*)d_in[4];
    const float* b2   = (const float*)d_in[5];
    const float* Wm1  = (const float*)d_in[6];
    const float* bm1  = (const float*)d_in[7];
    const float* Wm2  = (const float*)d_in[8];
    const float* bm2  = (const float*)d_in[9];
    float* out = (float*)d_out;

    int N = in_sizes[0] / IN_F;
    int E = in_sizes[1] / 2;
    const int* src = ei;
    const int* dst = ei + E;

    int*   degi;   cudaGetSymbolAddress((void**)&degi,   g_degi);
    int*   cursor; cudaGetSymbolAddress((void**)&cursor, g_cursor);
    float* hs1;  cudaGetSymbolAddress((void**)&hs1,  g_hs1);
    float* acc1; cudaGetSymbolAddress((void**)&acc1, g_acc1);
    float* hs2;  cudaGetSymbolAddress((void**)&hs2,  g_hs2);
    float* acc2; cudaGetSymbolAddress((void**)&acc2, g_acc2);

    int blocks_m = (N + 63) / 64;

    // Side stream + fork/join events (capture-time only)
    cudaStream_t s2;
    cudaEvent_t evFork, evCsr;
    cudaStreamCreateWithFlags(&s2, cudaStreamNonBlocking);
    cudaEventCreateWithFlags(&evFork, cudaEventDisableTiming);
    cudaEventCreateWithFlags(&evCsr,  cudaEventDisableTiming);

    // fork: CSR build on s2 || gemm1 on main
    cudaEventRecord(evFork, 0);
    cudaStreamWaitEvent(s2, evFork, 0);
    cudaMemsetAsync(degi, 0, (size_t)N * sizeof(int), s2);
    cudaMemsetAsync(cursor, 0, 4 * sizeof(int), s2);
    count_kernel<<<(E + 255) / 256, 256, 0, s2>>>(dst, E);
    assign_kernel<<<(N + 255) / 256, 256, 0, s2>>>(N);
    fill_kernel<<<(E + 255) / 256, 256, 0, s2>>>(src, dst, E);
    cudaEventRecord(evCsr, s2);

    gemm1_tiled<<<blocks_m, dim3(16, 16)>>>(x, W1, N);
    cudaStreamWaitEvent(0, evCsr, 0);

    // conv1: weighted gather (dinv applied per neighbor)
    gather_w_kernel<<<(N * 16 + 255) / 256, 256>>>(hs1, acc1, N);

    // conv2: GEMM pre-scales by dinv -> plain gather
    gemm2_tiled<<<blocks_m, dim3(16, 16)>>>(W2, b1, N);
    gather_p_kernel<<<(N * 16 + 255) / 256, 256>>>(hs2, acc2, N);

    // node-side MLP precompute
    gemm3_tiled<<<dim3(blocks_m, 2), dim3(16, 16)>>>(Wm1, b2, bm1, N);

    // edge MLP
    edge_kernel<<<(E + 255) / 256, 256>>>(src, dst, Wm2, bm2, out, E);
}

// round 17
// speedup vs baseline: 1.0485x; 1.0374x over previous
#include <cuda_runtime.h>
#include <cuda_bf16.h>
#include <cstdint>

// Problem constants (dataset fixed: N=50000, E=800000, IN=128, H=64, C=16)
#define MAXN 50016
#define MAXE 800000
#define H 64
#define IN_F 128
#define C_OUT 16

// Scratch (device globals; 16B aligned)
__device__ __align__(16) int   g_degi[MAXN];
__device__ __align__(16) int   g_rowptr[MAXN];
__device__ __align__(16) int   g_cursor[4];
__device__ __align__(16) int   g_col[MAXE];
__device__ __align__(16) float g_dinv[MAXN];
__device__ __align__(16) float g_hs1[MAXN * H];
__device__ __align__(16) float g_acc1[MAXN * H];
__device__ __align__(16) float g_hs2[MAXN * H];
__device__ __align__(16) float g_acc2[MAXN * H];
__device__ __align__(16) float g_A[MAXN * H];
__device__ __align__(16) float g_B[MAXN * H];

typedef unsigned long long ull;

__device__ __forceinline__ void ffma2(ull& acc, ull a, ull b) {
    asm("fma.rn.f32x2 %0, %1, %2, %0;" : "+l"(acc) : "l"(a), "l"(b));
}
__device__ __forceinline__ ull pk2(float a, float b) {
    ull r;
    asm("mov.b64 %0, {%1, %2};" : "=l"(r) : "f"(a), "f"(b));
    return r;
}
__device__ __forceinline__ float2 unpk(ull v) {
    float2 r;
    asm("mov.b64 {%0, %1}, %2;" : "=f"(r.x), "=f"(r.y) : "l"(v));
    return r;
}

// ---------------- CSR build (side stream, overlapped with gemm1)
__global__ void count_kernel(const int* __restrict__ dst, int E) {
    int e = blockIdx.x * blockDim.x + threadIdx.x;
    if (e < E) atomicAdd(&g_degi[dst[e]], 1);
}

// Warp-aggregated cursor allocation (1 atomic/warp) + dinv computation.
__global__ void assign_kernel(int N) {
    int n = blockIdx.x * blockDim.x + threadIdx.x;
    int lane = threadIdx.x & 31;
    int deg = (n < N) ? g_degi[n] : 0;

    int x = deg;
#pragma unroll
    for (int o = 1; o < 32; o <<= 1) {
        int y = __shfl_up_sync(0xffffffffu, x, o);
        if (lane >= o) x += y;
    }
    int total = __shfl_sync(0xffffffffu, x, 31);
    int base = 0;
    if (lane == 31) base = atomicAdd(&g_cursor[0], total);
    base = __shfl_sync(0xffffffffu, base, 31);

    if (n < N) {
        g_rowptr[n] = base + (x - deg);
        g_dinv[n] = rsqrtf((float)(deg + 1));
    }
}

// rowptr doubles as the fill cursor; after this kernel rowptr[n] = segment END.
__global__ void fill_kernel(const int* __restrict__ src, const int* __restrict__ dst, int E) {
    int e = blockIdx.x * blockDim.x + threadIdx.x;
    if (e >= E) return;
    int d = dst[e];
    int pos = atomicAdd(&g_rowptr[d], 1);
    g_col[pos] = src[e];
}

// ---------------- gather: out[n] = raw[n]*dinv[n] + sum_s raw[s]*dinv[s]
// 16 threads/node (float4 chunk each), MLP=8 unrolled inner loop.
__global__ void gather_kernel(const float* __restrict__ hs, float* __restrict__ out, int N) {
    int t = blockIdx.x * blockDim.x + threadIdx.x;
    int n = t >> 4;
    if (n >= N) return;
    int c = (t & 15) << 2;
    const float* hp = hs + c;

    float dn = g_dinv[n];
    float4 sv = *reinterpret_cast<const float4*>(hp + (size_t)n * H);  // self
    float4 acc = make_float4(sv.x * dn, sv.y * dn, sv.z * dn, sv.w * dn);

    int end = g_rowptr[n];
    int i = end - g_degi[n];
    for (; i + 8 <= end; i += 8) {
        int s0 = __ldg(&g_col[i + 0]);
        int s1 = __ldg(&g_col[i + 1]);
        int s2 = __ldg(&g_col[i + 2]);
        int s3 = __ldg(&g_col[i + 3]);
        int s4 = __ldg(&g_col[i + 4]);
        int s5 = __ldg(&g_col[i + 5]);
        int s6 = __ldg(&g_col[i + 6]);
        int s7 = __ldg(&g_col[i + 7]);
        float d0 = __ldg(&g_dinv[s0]);
        float d1 = __ldg(&g_dinv[s1]);
        float d2 = __ldg(&g_dinv[s2]);
        float d3 = __ldg(&g_dinv[s3]);
        float d4 = __ldg(&g_dinv[s4]);
        float d5 = __ldg(&g_dinv[s5]);
        float d6 = __ldg(&g_dinv[s6]);
        float d7 = __ldg(&g_dinv[s7]);
        float4 v0 = *reinterpret_cast<const float4*>(hp + (size_t)s0 * H);
        float4 v1 = *reinterpret_cast<const float4*>(hp + (size_t)s1 * H);
        float4 v2 = *reinterpret_cast<const float4*>(hp + (size_t)s2 * H);
        float4 v3 = *reinterpret_cast<const float4*>(hp + (size_t)s3 * H);
        float4 v4 = *reinterpret_cast<const float4*>(hp + (size_t)s4 * H);
        float4 v5 = *reinterpret_cast<const float4*>(hp + (size_t)s5 * H);
        float4 v6 = *reinterpret_cast<const float4*>(hp + (size_t)s6 * H);
        float4 v7 = *reinterpret_cast<const float4*>(hp + (size_t)s7 * H);
        acc.x += v0.x * d0 + v1.x * d1 + v2.x * d2 + v3.x * d3
               + v4.x * d4 + v5.x * d5 + v6.x * d6 + v7.x * d7;
        acc.y += v0.y * d0 + v1.y * d1 + v2.y * d2 + v3.y * d3
               + v4.y * d4 + v5.y * d5 + v6.y * d6 + v7.y * d7;
        acc.z += v0.z * d0 + v1.z * d1 + v2.z * d2 + v3.z * d3
               + v4.z * d4 + v5.z * d5 + v6.z * d6 + v7.z * d7;
        acc.w += v0.w * d0 + v1.w * d1 + v2.w * d2 + v3.w * d3
               + v4.w * d4 + v5.w * d5 + v6.w * d6 + v7.w * d7;
    }
    for (; i < end; i++) {
        int s = __ldg(&g_col[i]);
        float ds = __ldg(&g_dinv[s]);
        float4 v = *reinterpret_cast<const float4*>(hp + (size_t)s * H);
        acc.x += v.x * ds; acc.y += v.y * ds; acc.z += v.z * ds; acc.w += v.w * ds;
    }
    *reinterpret_cast<float4*>(out + (size_t)n * H + c) = acc;
}

// =====================================================================
// Tiled GEMMs (R2 proven form): M=64, N=64, 256 thr, 4x4 microtile
// =====================================================================

#define GEMM_MAIN()                                                             \
    _Pragma("unroll 8")                                                         \
    for (int kk = 0; kk < 64; kk++) {                                           \
        float4 b4 = *reinterpret_cast<const float4*>(&Ws[kk][tx * 4]);          \
        float a0 = As[ty * 4 + 0][kk];                                          \
        float a1 = As[ty * 4 + 1][kk];                                          \
        float a2 = As[ty * 4 + 2][kk];                                          \
        float a3 = As[ty * 4 + 3][kk];                                          \
        acc[0][0] += a0 * b4.x; acc[0][1] += a0 * b4.y; acc[0][2] += a0 * b4.z; acc[0][3] += a0 * b4.w; \
        acc[1][0] += a1 * b4.x; acc[1][1] += a1 * b4.y; acc[1][2] += a1 * b4.z; acc[1][3] += a1 * b4.w; \
        acc[2][0] += a2 * b4.x; acc[2][1] += a2 * b4.y; acc[2][2] += a2 * b4.z; acc[2][3] += a2 * b4.w; \
        acc[3][0] += a3 * b4.x; acc[3][1] += a3 * b4.y; acc[3][2] += a3 * b4.z; acc[3][3] += a3 * b4.w; \
    }

// conv1: hs1 = x @ W1 (RAW — fully independent of CSR chain)
__global__ __launch_bounds__(256) void gemm1_tiled(
    const float* __restrict__ x, const float* __restrict__ W1, int N) {
    __shared__ float As[64][68];
    __shared__ float Ws[64][68];
    const int tx = threadIdx.x, ty = threadIdx.y;
    const int t = ty * 16 + tx;
    const int lm = t >> 4;
    const int lk4 = (t & 15) * 4;
    const int m0 = blockIdx.x * 64;

    float acc[4][4];
#pragma unroll
    for (int i = 0; i < 4; i++)
#pragma unroll
        for (int j = 0; j < 4; j++) acc[i][j] = 0.f;

    for (int k0 = 0; k0 < IN_F; k0 += 64) {
        __syncthreads();
#pragma unroll
        for (int i = 0; i < 4; i++) {
            int m = lm + 16 * i;
            int gm = m0 + m;
            float4 v = make_float4(0.f, 0.f, 0.f, 0.f);
            if (gm < N) v = *reinterpret_cast<const float4*>(x + (size_t)gm * IN_F + k0 + lk4);
            *reinterpret_cast<float4*>(&As[m][lk4]) = v;
            int k = lm + 16 * i;
            float4 w = *reinterpret_cast<const float4*>(W1 + (size_t)(k0 + k) * H + lk4);
            *reinterpret_cast<float4*>(&Ws[k][lk4]) = w;
        }
        __syncthreads();
        GEMM_MAIN()
    }

#pragma unroll
    for (int i = 0; i < 4; i++) {
        int gm = m0 + ty * 4 + i;
        if (gm < N) {
            float4 r = make_float4(acc[i][0], acc[i][1], acc[i][2], acc[i][3]);
            *reinterpret_cast<float4*>(&g_hs1[(size_t)gm * H + tx * 4]) = r;
        }
    }
}

// conv2: h1 = relu(acc1*dinv + b1); hs2 = h1 @ W2 (RAW epilogue)
__global__ __launch_bounds__(256) void gemm2_tiled(
    const float* __restrict__ W2, const float* __restrict__ b1, int N) {
    __shared__ float As[64][68];
    __shared__ float Ws[64][68];
    const int tx = threadIdx.x, ty = threadIdx.y;
    const int t = ty * 16 + tx;
    const int lm = t >> 4;
    const int lk4 = (t & 15) * 4;
    const int m0 = blockIdx.x * 64;

    float4 bb = *reinterpret_cast<const float4*>(b1 + lk4);
#pragma unroll
    for (int i = 0; i < 4; i++) {
        int m = lm + 16 * i;
        int gm = m0 + m;
        float4 v = make_float4(0.f, 0.f, 0.f, 0.f);
        if (gm < N) {
            float di = g_dinv[gm];
            float4 a = *reinterpret_cast<const float4*>(&g_acc1[(size_t)gm * H + lk4]);
            v.x = fmaxf(a.x * di + bb.x, 0.f);
            v.y = fmaxf(a.y * di + bb.y, 0.f);
            v.z = fmaxf(a.z * di + bb.z, 0.f);
            v.w = fmaxf(a.w * di + bb.w, 0.f);
        }
        *reinterpret_cast<float4*>(&As[m][lk4]) = v;
        int k = lm + 16 * i;
        float4 w = *reinterpret_cast<const float4*>(W2 + (size_t)k * H + lk4);
        *reinterpret_cast<float4*>(&Ws[k][lk4]) = w;
    }
    __syncthreads();

    float acc[4][4];
#pragma unroll
    for (int i = 0; i < 4; i++)
#pragma unroll
        for (int j = 0; j < 4; j++) acc[i][j] = 0.f;

    GEMM_MAIN()

#pragma unroll
    for (int i = 0; i < 4; i++) {
        int gm = m0 + ty * 4 + i;
        if (gm < N) {
            float4 r = make_float4(acc[i][0], acc[i][1], acc[i][2], acc[i][3]);
            *reinterpret_cast<float4*>(&g_hs2[(size_t)gm * H + tx * 4]) = r;
        }
    }
}

// node MLP precompute: h2 = relu(acc2*dinv + b2)
// half=0: g_A = h2 @ Wm1[0:64] + bm1 ; half=1: g_B = h2 @ Wm1[64:128]
__global__ __launch_bounds__(256) void gemm3_tiled(
    const float* __restrict__ Wm1, const float* __restrict__ b2,
    const float* __restrict__ bm1, int N) {
    __shared__ float As[64][68];
    __shared__ float Ws[64][68];
    const int tx = threadIdx.x, ty = threadIdx.y;
    const int t = ty * 16 + tx;
    const int lm = t >> 4;
    const int lk4 = (t & 15) * 4;
    const int m0 = blockIdx.x * 64;
    const int half = blockIdx.y;

    float4 bb = *reinterpret_cast<const float4*>(b2 + lk4);
#pragma unroll
    for (int i = 0; i < 4; i++) {
        int m = lm + 16 * i;
        int gm = m0 + m;
        float4 v = make_float4(0.f, 0.f, 0.f, 0.f);
        if (gm < N) {
            float di = g_dinv[gm];
            float4 a = *reinterpret_cast<const float4*>(&g_acc2[(size_t)gm * H + lk4]);
            v.x = fmaxf(a.x * di + bb.x, 0.f);
            v.y = fmaxf(a.y * di + bb.y, 0.f);
            v.z = fmaxf(a.z * di + bb.z, 0.f);
            v.w = fmaxf(a.w * di + bb.w, 0.f);
        }
        *reinterpret_cast<float4*>(&As[m][lk4]) = v;
        int k = lm + 16 * i;
        float4 w = *reinterpret_cast<const float4*>(Wm1 + (size_t)(half * H + k) * H + lk4);
        *reinterpret_cast<float4*>(&Ws[k][lk4]) = w;
    }
    __syncthreads();

    float acc[4][4];
#pragma unroll
    for (int i = 0; i < 4; i++)
#pragma unroll
        for (int j = 0; j < 4; j++) acc[i][j] = 0.f;

    GEMM_MAIN()

    float4 badd = make_float4(0.f, 0.f, 0.f, 0.f);
    if (half == 0) badd = *reinterpret_cast<const float4*>(bm1 + tx * 4);
    float* outbuf = (half == 0) ? g_A : g_B;
#pragma unroll
    for (int i = 0; i < 4; i++) {
        int gm = m0 + ty * 4 + i;
        if (gm < N) {
            float4 r = make_float4(acc[i][0] + badd.x, acc[i][1] + badd.y,
                                   acc[i][2] + badd.z, acc[i][3] + badd.w);
            *reinterpret_cast<float4*>(&outbuf[(size_t)gm * H + tx * 4]) = r;
        }
    }
}

// ---------------- edge MLP: out[e] = relu(A[src]+B[dst]) @ Wm2 + bm2 (f32x2)
__global__ void edge_kernel(const int* __restrict__ src, const int* __restrict__ dst,
                            const float* __restrict__ Wm2, const float* __restrict__ bm2,
                            float* __restrict__ out, int E) {
    __shared__ float Ws[H * C_OUT];
    __shared__ float bs[C_OUT];
    int tid = threadIdx.x;
    for (int i = tid; i < H * C_OUT; i += blockDim.x) Ws[i] = Wm2[i];
    if (tid < C_OUT) bs[tid] = bm2[tid];
    __syncthreads();

    int e = blockIdx.x * blockDim.x + tid;
    if (e >= E) return;
    int s = src[e], d = dst[e];
    const float4* Ap = reinterpret_cast<const float4*>(g_A + (size_t)s * H);
    const float4* Bp = reinterpret_cast<const float4*>(g_B + (size_t)d * H);

    ull acc2[8];
#pragma unroll
    for (int j = 0; j < 8; j++) acc2[j] = pk2(bs[2 * j], bs[2 * j + 1]);

#pragma unroll
    for (int q = 0; q < H / 4; q++) {
        float4 a4 = Ap[q];
        float4 b4 = Bp[q];
        ull zp[4];
        zp[0] = pk2(fmaxf(a4.x + b4.x, 0.f), fmaxf(a4.x + b4.x, 0.f));
        zp[1] = pk2(fmaxf(a4.y + b4.y, 0.f), fmaxf(a4.y + b4.y, 0.f));
        zp[2] = pk2(fmaxf(a4.z + b4.z, 0.f), fmaxf(a4.z + b4.z, 0.f));
        zp[3] = pk2(fmaxf(a4.w + b4.w, 0.f), fmaxf(a4.w + b4.w, 0.f));
#pragma unroll
        for (int kk = 0; kk < 4; kk++) {
            const ulonglong2* wrow = reinterpret_cast<const ulonglong2*>(Ws + (q * 4 + kk) * C_OUT);
#pragma unroll
            for (int j = 0; j < 4; j++) {
                ulonglong2 w2 = wrow[j];
                ffma2(acc2[2 * j + 0], zp[kk], w2.x);
                ffma2(acc2[2 * j + 1], zp[kk], w2.y);
            }
        }
    }

    float4* op = reinterpret_cast<float4*>(out + (size_t)e * C_OUT);
#pragma unroll
    for (int c = 0; c < 4; c++) {
        float2 p0 = unpk(acc2[2 * c + 0]);
        float2 p1 = unpk(acc2[2 * c + 1]);
        op[c] = make_float4(p0.x, p0.y, p1.x, p1.y);
    }
}

extern "C" void kernel_launch(void* const* d_in, const int* in_sizes, int n_in,
                              void* d_out, int out_size) {
    const float* x    = (const float*)d_in[0];
    const int*   ei   = (const int*)d_in[1];
    const float* W1   = (const float*)d_in[2];
    const float* b1   = (const float*)d_in[3];
    const float* W2   = (const float*)d_in[4];
    const float* b2   = (const float*)d_in[5];
    const float* Wm1  = (const float*)d_in[6];
    const float* bm1  = (const float*)d_in[7];
    const float* Wm2  = (const float*)d_in[8];
    const float* bm2  = (const float*)d_in[9];
    float* out = (float*)d_out;

    int N = in_sizes[0] / IN_F;
    int E = in_sizes[1] / 2;
    const int* src = ei;
    const int* dst = ei + E;

    int*   degi;   cudaGetSymbolAddress((void**)&degi,   g_degi);
    int*   cursor; cudaGetSymbolAddress((void**)&cursor, g_cursor);
    float* hs1;  cudaGetSymbolAddress((void**)&hs1,  g_hs1);
    float* acc1; cudaGetSymbolAddress((void**)&acc1, g_acc1);
    float* hs2;  cudaGetSymbolAddress((void**)&hs2,  g_hs2);
    float* acc2; cudaGetSymbolAddress((void**)&acc2, g_acc2);

    int blocks_m = (N + 63) / 64;

    // Side stream + fork/join events (created during capture; capture-time only)
    cudaStream_t s2;
    cudaEvent_t evFork, evCsr;
    cudaStreamCreateWithFlags(&s2, cudaStreamNonBlocking);
    cudaEventCreateWithFlags(&evFork, cudaEventDisableTiming);
    cudaEventCreateWithFlags(&evCsr,  cudaEventDisableTiming);

    // fork: CSR build on s2 || gemm1 on main
    cudaEventRecord(evFork, 0);
    cudaStreamWaitEvent(s2, evFork, 0);
    cudaMemsetAsync(degi, 0, (size_t)N * sizeof(int), s2);
    cudaMemsetAsync(cursor, 0, 4 * sizeof(int), s2);
    count_kernel<<<(E + 255) / 256, 256, 0, s2>>>(dst, E);
    assign_kernel<<<(N + 255) / 256, 256, 0, s2>>>(N);
    fill_kernel<<<(E + 255) / 256, 256, 0, s2>>>(src, dst, E);
    cudaEventRecord(evCsr, s2);

    gemm1_tiled<<<blocks_m, dim3(16, 16)>>>(x, W1, N);
    cudaStreamWaitEvent(0, evCsr, 0);

    // conv1 aggregate
    gather_kernel<<<(N * 16 + 255) / 256, 256>>>(hs1, acc1, N);

    // conv2
    gemm2_tiled<<<blocks_m, dim3(16, 16)>>>(W2, b1, N);
    gather_kernel<<<(N * 16 + 255) / 256, 256>>>(hs2, acc2, N);

    // node-side MLP precompute
    gemm3_tiled<<<dim3(blocks_m, 2), dim3(16, 16)>>>(Wm1, b2, bm1, N);

    // edge MLP
    edge_kernel<<<(E + 255) / 256, 256>>>(src, dst, Wm2, bm2, out, E);
}